// round 12
// baseline (speedup 1.0000x reference)
#include <cuda_runtime.h>
#include <cuda_bf16.h>
#include <math.h>
#include <stdint.h>

#define BQ   8
#define CC   256
#define HH   128
#define WWD  128
#define GG   16
#define NWIN 512
#define NT   256
#define C8   32
#define FF   1024
#define HW   16384

// ---------------- device scratch ----------------
__device__ __align__(128) float g_xa[(size_t)BQ * CC * HH * WWD];

// ================= helpers =================
__device__ __forceinline__ uint32_t smem_u32(const void* p) {
    uint32_t a;
    asm("{ .reg .u64 t; cvta.to.shared.u64 t, %1; cvt.u32.u64 %0, t; }" : "=r"(a) : "l"(p));
    return a;
}
__device__ __forceinline__ float tf32r(float v) {
    uint32_t r; asm("cvt.rna.tf32.f32 %0, %1;" : "=r"(r) : "f"(v));
    return __uint_as_float(r);
}
__device__ __forceinline__ void mma_tf32(float* d, float a0, float a1, float a2, float a3,
                                         float b0, float b1) {
    asm volatile(
        "mma.sync.aligned.m16n8k8.row.col.f32.tf32.tf32.f32 "
        "{%0,%1,%2,%3}, {%4,%5,%6,%7}, {%8,%9}, {%0,%1,%2,%3};"
        : "+f"(d[0]), "+f"(d[1]), "+f"(d[2]), "+f"(d[3])
        : "r"(__float_as_uint(a0)), "r"(__float_as_uint(a1)),
          "r"(__float_as_uint(a2)), "r"(__float_as_uint(a3)),
          "r"(__float_as_uint(b0)), "r"(__float_as_uint(b1)));
}
__device__ __forceinline__ void mma_bf16(float* d, uint32_t a0, uint32_t a1, uint32_t a2, uint32_t a3,
                                         uint32_t b0, uint32_t b1) {
    asm volatile(
        "mma.sync.aligned.m16n8k16.row.col.f32.bf16.bf16.f32 "
        "{%0,%1,%2,%3}, {%4,%5,%6,%7}, {%8,%9}, {%0,%1,%2,%3};"
        : "+f"(d[0]), "+f"(d[1]), "+f"(d[2]), "+f"(d[3])
        : "r"(a0), "r"(a1), "r"(a2), "r"(a3), "r"(b0), "r"(b1));
}
__device__ __forceinline__ uint32_t packbf(float a, float b) {
    __nv_bfloat162 h = __float22bfloat162_rn(make_float2(a, b));
    return *(uint32_t*)&h;
}
#define CP16(dst, src) asm volatile("cp.async.cg.shared.global [%0], [%1], 16;" :: "r"(dst), "l"(src))
#define CP_COMMIT()    asm volatile("cp.async.commit_group;" ::: "memory")
#define CP_WAIT1()     asm volatile("cp.async.wait_group 1;" ::: "memory")
#define CP_WAIT0()     asm volatile("cp.async.wait_group 0;" ::: "memory")

__device__ __forceinline__ float gelu_exact(float v) { return v * normcdff(v); }

// ------------------------------------------------------------------
// Kernel 1: FUSED window attention, 2 CTAs/SM (no XS tile; x B-operands
// read from global/L2 and packed to bf16 at fragment build).
// smem: ES [32][264]bf16 @0 (alias WQS) | TS @16896 (alias WKS)
//       QS [256][36]bf16 @33792 | KS @52224 | RED @70656 (128 f)
// ------------------------------------------------------------------
#define AT_ES  0
#define AT_WQS 0
#define AT_TS  16896
#define AT_WKS 16896
#define AT_QS  33792
#define AT_KS  52224
#define AT_RED 70656
#define AT_SMEM 71424

__global__ void __launch_bounds__(256, 2) attn_fused_kernel(const float* __restrict__ x,
                                                            const float* __restrict__ Wq,
                                                            const float* __restrict__ Wk,
                                                            const float* __restrict__ Wv,
                                                            const float* __restrict__ gamma)
{
    extern __shared__ __align__(16) char sp[];
    const int tid = threadIdx.x, lane = tid & 31, wp = tid >> 5;
    const int g = lane >> 2, t = lane & 3;
    const int w = blockIdx.x, b = w >> 6, ih = (w >> 3) & 7, iw = w & 7;

    const float* xw = x + (size_t)b * CC * HW + ih * GG * WWD + iw * GG;
    const float gam = __ldg(gamma);

    // ---- stage Wq/Wk -> WQS/WKS bf16 [32o][264c] ----
    for (int it = 0; it < 16; it++) {
        int i = it * 256 + tid;
        int o = i >> 7, cp2 = (i & 127) * 2;
        float2 q2 = *(const float2*)(Wq + (size_t)o * CC + cp2);
        *(uint32_t*)(sp + AT_WQS + o * 528 + cp2 * 2) = packbf(q2.x, q2.y);
        float2 k2 = *(const float2*)(Wk + (size_t)o * CC + cp2);
        *(uint32_t*)(sp + AT_WKS + o * 528 + cp2 * 2) = packbf(k2.x, k2.y);
    }
    __syncthreads();

    // ================= qk-GEMM: D[32o][256tok]; warp owns 32 tokens =================
    // B built from global x: 4 strided LDG.32 per fragment.
    {
        const int n0 = wp * 32;
        float Dq[2][4][4], Dk[2][4][4];
#pragma unroll
        for (int mi = 0; mi < 2; mi++)
#pragma unroll
            for (int nf = 0; nf < 4; nf++)
#pragma unroll
                for (int r = 0; r < 4; r++) { Dq[mi][nf][r] = 0.f; Dk[mi][nf][r] = 0.f; }

#pragma unroll 4
        for (int ks = 0; ks < 16; ks++) {
            uint32_t Aq[2][4], Ak[2][4];
#pragma unroll
            for (int mi = 0; mi < 2; mi++) {
                const char* aq = sp + AT_WQS + (mi * 16 + g) * 528 + ks * 32 + t * 4;
                Aq[mi][0] = *(const uint32_t*)aq;
                Aq[mi][1] = *(const uint32_t*)(aq + 8 * 528);
                Aq[mi][2] = *(const uint32_t*)(aq + 16);
                Aq[mi][3] = *(const uint32_t*)(aq + 8 * 528 + 16);
                const char* ak = sp + AT_WKS + (mi * 16 + g) * 528 + ks * 32 + t * 4;
                Ak[mi][0] = *(const uint32_t*)ak;
                Ak[mi][1] = *(const uint32_t*)(ak + 8 * 528);
                Ak[mi][2] = *(const uint32_t*)(ak + 16);
                Ak[mi][3] = *(const uint32_t*)(ak + 8 * 528 + 16);
            }
            int c0k = ks * 16 + 2 * t;
#pragma unroll
            for (int nf = 0; nf < 4; nf++) {
                int tok = n0 + nf * 8 + g;
                int p = (tok >> 4) * WWD + (tok & 15);
                const float* xp = xw + (size_t)c0k * HW + p;
                uint32_t b0 = packbf(xp[0], xp[HW]);
                uint32_t b1 = packbf(xp[8 * HW], xp[9 * HW]);
#pragma unroll
                for (int mi = 0; mi < 2; mi++) {
                    mma_bf16(Dq[mi][nf], Aq[mi][0], Aq[mi][1], Aq[mi][2], Aq[mi][3], b0, b1);
                    mma_bf16(Dk[mi][nf], Ak[mi][0], Ak[mi][1], Ak[mi][2], Ak[mi][3], b0, b1);
                }
            }
        }
        __nv_bfloat16* qs = (__nv_bfloat16*)(sp + AT_QS);
        __nv_bfloat16* ksm = (__nv_bfloat16*)(sp + AT_KS);
#pragma unroll
        for (int mi = 0; mi < 2; mi++)
#pragma unroll
            for (int nf = 0; nf < 4; nf++) {
                int o_lo = mi * 16 + g, o_hi = o_lo + 8;
                int tok = n0 + nf * 8 + 2 * t;
                qs[tok * 36 + o_lo] = __float2bfloat16(Dq[mi][nf][0]);
                qs[(tok + 1) * 36 + o_lo] = __float2bfloat16(Dq[mi][nf][1]);
                qs[tok * 36 + o_hi] = __float2bfloat16(Dq[mi][nf][2]);
                qs[(tok + 1) * 36 + o_hi] = __float2bfloat16(Dq[mi][nf][3]);
                ksm[tok * 36 + o_lo] = __float2bfloat16(Dk[mi][nf][0]);
                ksm[(tok + 1) * 36 + o_lo] = __float2bfloat16(Dk[mi][nf][1]);
                ksm[tok * 36 + o_hi] = __float2bfloat16(Dk[mi][nf][2]);
                ksm[(tok + 1) * 36 + o_hi] = __float2bfloat16(Dk[mi][nf][3]);
            }
    }
    __syncthreads();   // QS/KS visible; WQS/WKS dead -> ES/TS live

    const int wm2 = wp >> 2, wn = wp & 3;
    const int m0s = wm2 * 16, n0s = wn * 64;
    const int c0 = wp * 32;
    float* red = (float*)(sp + AT_RED);
    float* xab = g_xa + (size_t)b * CC * HW + ih * GG * WWD + iw * GG;

    for (int mq = 0; mq < 8; mq++) {
        const int mqb = mq * 32;

        // ===== S-GEMM: S[32m][256n]; warp = 16m x 64n =====
        float S[8][4];
#pragma unroll
        for (int ni = 0; ni < 8; ni++)
#pragma unroll
            for (int r = 0; r < 4; r++) S[ni][r] = 0.f;

#pragma unroll
        for (int ks = 0; ks < 2; ks++) {
            const char* ab = sp + AT_QS + (mqb + m0s + g) * 72 + ks * 32 + t * 4;
            uint32_t a0 = *(const uint32_t*)ab;
            uint32_t a1 = *(const uint32_t*)(ab + 8 * 72);
            uint32_t a2 = *(const uint32_t*)(ab + 16);
            uint32_t a3 = *(const uint32_t*)(ab + 8 * 72 + 16);
#pragma unroll
            for (int ni = 0; ni < 8; ni++) {
                const char* bb = sp + AT_KS + (n0s + ni * 8 + g) * 72 + ks * 32 + t * 4;
                uint32_t b0 = *(const uint32_t*)bb;
                uint32_t b1 = *(const uint32_t*)(bb + 16);
                mma_bf16(S[ni], a0, a1, a2, a3, b0, b1);
            }
        }

        // ===== max-free softmax =====
        float sum0 = 0.f, sum1 = 0.f;
#pragma unroll
        for (int ni = 0; ni < 8; ni++) {
            float e0 = __expf(S[ni][0]);
            float e1 = __expf(S[ni][1]);
            float e2 = __expf(S[ni][2]);
            float e3 = __expf(S[ni][3]);
            sum0 += e0 + e1;
            sum1 += e2 + e3;
            int ncol = (n0s + ni * 8 + 2 * t) * 2;
            *(uint32_t*)(sp + AT_ES + (m0s + g) * 528 + ncol) = packbf(e0, e1);
            *(uint32_t*)(sp + AT_ES + (m0s + g + 8) * 528 + ncol) = packbf(e2, e3);
        }
        sum0 += __shfl_xor_sync(0xffffffff, sum0, 1);
        sum0 += __shfl_xor_sync(0xffffffff, sum0, 2);
        sum1 += __shfl_xor_sync(0xffffffff, sum1, 1);
        sum1 += __shfl_xor_sync(0xffffffff, sum1, 2);
        if (t == 0) {
            red[wn * 32 + m0s + g] = sum0;
            red[wn * 32 + m0s + g + 8] = sum1;
        }
        __syncthreads();   // ES + red visible

        float zrv[2][2];
#pragma unroll
        for (int mi = 0; mi < 2; mi++)
#pragma unroll
            for (int h = 0; h < 2; h++) {
                int row = mi * 16 + g + 8 * h;
                zrv[mi][h] = gam / (red[row] + red[32 + row] + red[64 + row] + red[96 + row]);
            }

        // ===== t-GEMM: Dt[32m][256c]; warp = 32m x 32c; B from global x =====
        float Dt[2][4][4];
#pragma unroll
        for (int mi = 0; mi < 2; mi++)
#pragma unroll
            for (int ci = 0; ci < 4; ci++)
#pragma unroll
                for (int r = 0; r < 4; r++) Dt[mi][ci][r] = 0.f;

#pragma unroll 4
        for (int kk = 0; kk < 16; kk++) {
            uint32_t A[2][4];
#pragma unroll
            for (int mi = 0; mi < 2; mi++) {
                const char* ab = sp + AT_ES + (mi * 16 + g) * 528 + kk * 32 + t * 4;
                A[mi][0] = *(const uint32_t*)ab;
                A[mi][1] = *(const uint32_t*)(ab + 8 * 528);
                A[mi][2] = *(const uint32_t*)(ab + 16);
                A[mi][3] = *(const uint32_t*)(ab + 8 * 528 + 16);
            }
#pragma unroll
            for (int ci = 0; ci < 4; ci++) {
                const float* xr = xw + (size_t)(c0 + ci * 8 + g) * HW + kk * WWD;
                float2 f0 = *(const float2*)(xr + 2 * t);
                float2 f1 = *(const float2*)(xr + 8 + 2 * t);
                uint32_t b0 = packbf(f0.x, f0.y);
                uint32_t b1 = packbf(f1.x, f1.y);
#pragma unroll
                for (int mi = 0; mi < 2; mi++)
                    mma_bf16(Dt[mi][ci], A[mi][0], A[mi][1], A[mi][2], A[mi][3], b0, b1);
            }
        }
        // write TS (separate region; no barrier needed before write)
#pragma unroll
        for (int mi = 0; mi < 2; mi++)
#pragma unroll
            for (int ci = 0; ci < 4; ci++) {
                int ccol = (c0 + ci * 8 + 2 * t) * 2;
                *(uint32_t*)(sp + AT_TS + (mi * 16 + g) * 528 + ccol) = packbf(Dt[mi][ci][0], Dt[mi][ci][1]);
                *(uint32_t*)(sp + AT_TS + (mi * 16 + g + 8) * 528 + ccol) = packbf(Dt[mi][ci][2], Dt[mi][ci][3]);
            }
        __syncthreads();   // TS visible; all ES reads done

        // ===== out-GEMM: Do[32m][256co]; warp = 32m x 32co; B = Wv (global) =====
        float Do[2][4][4];
#pragma unroll
        for (int mi = 0; mi < 2; mi++)
#pragma unroll
            for (int cj = 0; cj < 4; cj++)
#pragma unroll
                for (int r = 0; r < 4; r++) Do[mi][cj][r] = 0.f;

#pragma unroll 4
        for (int kk = 0; kk < 16; kk++) {
            uint32_t A[2][4];
#pragma unroll
            for (int mi = 0; mi < 2; mi++) {
                const char* ab = sp + AT_TS + (mi * 16 + g) * 528 + kk * 32 + t * 4;
                A[mi][0] = *(const uint32_t*)ab;
                A[mi][1] = *(const uint32_t*)(ab + 8 * 528);
                A[mi][2] = *(const uint32_t*)(ab + 16);
                A[mi][3] = *(const uint32_t*)(ab + 8 * 528 + 16);
            }
#pragma unroll
            for (int cj = 0; cj < 4; cj++) {
                const float* wv = Wv + (size_t)(c0 + cj * 8 + g) * CC + kk * 16 + 2 * t;
                float2 f0 = *(const float2*)wv;
                float2 f1 = *(const float2*)(wv + 8);
                uint32_t b0 = packbf(f0.x, f0.y);
                uint32_t b1 = packbf(f1.x, f1.y);
#pragma unroll
                for (int mi = 0; mi < 2; mi++)
                    mma_bf16(Do[mi][cj], A[mi][0], A[mi][1], A[mi][2], A[mi][3], b0, b1);
            }
        }

        // ===== epilogue: gamma*out/z + x -> g_xa =====
#pragma unroll
        for (int mi = 0; mi < 2; mi++) {
            float z0 = zrv[mi][0], z1 = zrv[mi][1];
            int tok0 = mqb + mi * 16 + g, tok1 = tok0 + 8;
            int p0 = (tok0 >> 4) * WWD + (tok0 & 15);
            int p1 = (tok1 >> 4) * WWD + (tok1 & 15);
#pragma unroll
            for (int cj = 0; cj < 4; cj++) {
                int co = c0 + cj * 8 + 2 * t;
                size_t o00 = (size_t)co * HW + p0;
                size_t o01 = (size_t)(co + 1) * HW + p0;
                size_t o10 = (size_t)co * HW + p1;
                size_t o11 = (size_t)(co + 1) * HW + p1;
                xab[o00] = Do[mi][cj][0] * z0 + xw[o00];
                xab[o01] = Do[mi][cj][1] * z0 + xw[o01];
                xab[o10] = Do[mi][cj][2] * z1 + xw[o10];
                xab[o11] = Do[mi][cj][3] * z1 + xw[o11];
            }
        }
    }
}

// ------------------------------------------------------------------
// Kernel 2: tf32 FFN (R8/R11 pipelined version, unchanged)
// ------------------------------------------------------------------
#define XS_OFF 0
#define HS_OFF 33792
#define W1_OFF 38016
#define W2_OFF 46336
#define FFN_SMEM_FLOATS 55552
#define FFN_SMEM_BYTES (FFN_SMEM_FLOATS * 4)

__global__ void __launch_bounds__(256) ffn_mma_kernel(const float* __restrict__ W1,
                                                      const float* __restrict__ b1,
                                                      const float* __restrict__ W2,
                                                      const float* __restrict__ b2,
                                                      const float* __restrict__ ln1w,
                                                      const float* __restrict__ ln1b,
                                                      const float* __restrict__ ln2w,
                                                      const float* __restrict__ ln2b,
                                                      float* __restrict__ out)
{
    extern __shared__ __align__(16) float sm[];
    float* xs  = sm + XS_OFF;
    float* hs  = sm + HS_OFF;
    float* w1s = sm + W1_OFF;
    float* w2s = sm + W2_OFF;
    const uint32_t w1u = smem_u32(w1s);
    const uint32_t w2u = smem_u32(w2s);

    const int tid = threadIdx.x, lane = tid & 31, wp = tid >> 5;
    const int g = lane >> 2, t = lane & 3;
    const int blk = blockIdx.x, b = blk >> 7, row = blk & 127;

    const int fr0 = (wp >> 2) * 16;
    const int px0 = (wp & 3) * 32;
    const int pxm0 = (wp & 3) * 32;
    const int c0w = (wp >> 2) * 128;

    for (int j = 0; j < 8; j++) {
        int id = tid + j * 256;
        int f = id >> 6, seg = id & 63;
        CP16(w1u + (uint32_t)(f * 260 + seg * 4) * 4u, W1 + (size_t)f * CC + seg * 4);
    }
    CP_COMMIT();
    for (int j = 0; j < 8; j++) {
        int id = tid + j * 256;
        int c = id >> 3, seg = id & 7;
        CP16(w2u + (uint32_t)(c * 36 + seg * 4) * 4u, W2 + (size_t)c * FF + seg * 4);
    }
    CP_COMMIT();

    {
        const float* xab = g_xa + (size_t)b * CC * HW + (size_t)row * WWD;
        int px = tid & 127, ch = tid >> 7;
#pragma unroll 8
        for (int it = 0; it < 128; it++) {
            int c = ch + it * 2;
            xs[c * 132 + px] = tf32r(xab[(size_t)c * HW + px]);
        }
    }

    float yacc[2][16][4];
#pragma unroll
    for (int mf = 0; mf < 2; mf++)
#pragma unroll
        for (int nf = 0; nf < 16; nf++)
#pragma unroll
            for (int r = 0; r < 4; r++) yacc[mf][nf][r] = 0.f;

    const float* wr0 = w1s + (fr0 + g) * 260;
    const float* wr1 = wr0 + 8 * 260;
    const float* xb0 = xs + t * 132 + px0 + g;

    float d1[4][4];
#pragma unroll
    for (int nf = 0; nf < 4; nf++)
#pragma unroll
        for (int r = 0; r < 4; r++) d1[nf][r] = 0.f;

    CP_WAIT1();
    __syncthreads();
#pragma unroll 8
    for (int ks = 0; ks < 32; ks++) {
        int k = ks * 8;
        float a0 = wr0[k + t], a1 = wr1[k + t];
        float a2 = wr0[k + t + 4], a3 = wr1[k + t + 4];
        const float* xk = xb0 + k * 132;
#pragma unroll
        for (int nf = 0; nf < 4; nf++)
            mma_tf32(d1[nf], a0, a1, a2, a3, xk[nf * 8], xk[4 * 132 + nf * 8]);
    }
    __syncthreads();
    {
        const float* src = W1 + (size_t)32 * CC;
        for (int j = 0; j < 8; j++) {
            int id = tid + j * 256;
            int f = id >> 6, seg = id & 63;
            CP16(w1u + (uint32_t)(f * 260 + seg * 4) * 4u, src + (size_t)f * CC + seg * 4);
        }
        CP_COMMIT();
    }

    for (int ft = 0; ft < 32; ft++) {
        const int ftb = ft * 32;

        {
            float b1a = __ldg(&b1[ftb + fr0 + g]);
            float b1b = __ldg(&b1[ftb + fr0 + g + 8]);
#pragma unroll
            for (int nf = 0; nf < 4; nf++) {
                int px = px0 + nf * 8 + 2 * t;
                float2 v01 = make_float2(tf32r(gelu_exact(d1[nf][0] + b1a)),
                                         tf32r(gelu_exact(d1[nf][1] + b1a)));
                float2 v23 = make_float2(tf32r(gelu_exact(d1[nf][2] + b1b)),
                                         tf32r(gelu_exact(d1[nf][3] + b1b)));
                *(float2*)&hs[(fr0 + g) * 132 + px] = v01;
                *(float2*)&hs[(fr0 + g + 8) * 132 + px] = v23;
            }
        }
        CP_WAIT0();
        __syncthreads();

        float d1n[4][4];
#pragma unroll
        for (int nf = 0; nf < 4; nf++)
#pragma unroll
            for (int r = 0; r < 4; r++) d1n[nf][r] = 0.f;

        const bool more = (ft < 31);
#pragma unroll
        for (int ks2 = 0; ks2 < 4; ks2++) {
            const int k2 = ks2 * 8;
            float am[2][4];
#pragma unroll
            for (int mf = 0; mf < 2; mf++) {
                const float* hb = hs + (k2 + t) * 132 + pxm0 + 16 * mf + g;
                am[mf][0] = hb[0];
                am[mf][1] = hb[8];
                am[mf][2] = hb[4 * 132];
                am[mf][3] = hb[4 * 132 + 8];
            }
#pragma unroll
            for (int jj = 0; jj < 8; jj++) {
                if (more) {
                    int k = (ks2 * 8 + jj) * 8;
                    float a0 = wr0[k + t], a1 = wr1[k + t];
                    float a2 = wr0[k + t + 4], a3 = wr1[k + t + 4];
                    const float* xk = xb0 + k * 132;
#pragma unroll
                    for (int nf = 0; nf < 4; nf++)
                        mma_tf32(d1n[nf], a0, a1, a2, a3, xk[nf * 8], xk[4 * 132 + nf * 8]);
                }
#pragma unroll
                for (int u = 0; u < 2; u++) {
                    int nf = jj * 2 + u;
                    const float* wb = w2s + (c0w + nf * 8 + g) * 36 + k2 + t;
                    float b0 = wb[0], b1v = wb[4];
                    mma_tf32(yacc[0][nf], am[0][0], am[0][1], am[0][2], am[0][3], b0, b1v);
                    mma_tf32(yacc[1][nf], am[1][0], am[1][1], am[1][2], am[1][3], b0, b1v);
                }
            }
        }
        __syncthreads();

        if (ft < 31) {
            const float* src2 = W2 + (size_t)(ftb + 32);
            for (int j = 0; j < 8; j++) {
                int id = tid + j * 256;
                int c = id >> 3, seg = id & 7;
                CP16(w2u + (uint32_t)(c * 36 + seg * 4) * 4u, src2 + (size_t)c * FF + seg * 4);
            }
            if (ft < 30) {
                const float* src1 = W1 + (size_t)(ftb + 64) * CC;
                for (int j = 0; j < 8; j++) {
                    int id = tid + j * 256;
                    int f = id >> 6, seg = id & 63;
                    CP16(w1u + (uint32_t)(f * 260 + seg * 4) * 4u, src1 + (size_t)f * CC + seg * 4);
                }
            }
            CP_COMMIT();
        }

#pragma unroll
        for (int nf = 0; nf < 4; nf++)
#pragma unroll
            for (int r = 0; r < 4; r++) d1[nf][r] = d1n[nf][r];
    }
    __syncthreads();

    float* ys = sm;
#pragma unroll
    for (int nf = 0; nf < 16; nf++) {
        int c = c0w + nf * 8 + 2 * t;
        float b2a = __ldg(&b2[c]);
        float b2b = __ldg(&b2[c + 1]);
#pragma unroll
        for (int mf = 0; mf < 2; mf++) {
            int pxr = pxm0 + 16 * mf + g;
            *(float2*)&ys[pxr * 260 + c] =
                make_float2(yacc[mf][nf][0] + b2a, yacc[mf][nf][1] + b2b);
            *(float2*)&ys[(pxr + 8) * 260 + c] =
                make_float2(yacc[mf][nf][2] + b2a, yacc[mf][nf][3] + b2b);
        }
    }
    __syncthreads();

    int px = tid >> 1, hf = tid & 1;
    float* yrow = ys + px * 260 + hf * 128;
    float* red = hs;

    float s1 = 0.f, s2 = 0.f;
#pragma unroll 8
    for (int i = 0; i < 128; i += 4) {
        float4 v = *(float4*)&yrow[i];
        s1 += v.x + v.y + v.z + v.w;
        s2 += v.x * v.x + v.y * v.y + v.z * v.z + v.w * v.w;
    }
    red[tid] = s1; red[512 + tid] = s2;
    __syncthreads();
    float mu = (red[px * 2] + red[px * 2 + 1]) * (1.f / 256.f);
    float va = (red[512 + px * 2] + red[512 + px * 2 + 1]) * (1.f / 256.f);
    float rstd = rsqrtf(va - mu * mu + 1e-5f);

    const float* xsrc = g_xa + ((size_t)(b * CC) + hf * 128) * HW + (size_t)row * WWD + px;
    float t1 = 0.f, t2 = 0.f;
    for (int i = 0; i < 128; i++) {
        int c = hf * 128 + i;
        float x2v = xsrc[(size_t)i * HW] + (yrow[i] - mu) * rstd * ln1w[c] + ln1b[c];
        yrow[i] = x2v;
        t1 += x2v; t2 += x2v * x2v;
    }
    __syncthreads();
    red[tid] = t1; red[512 + tid] = t2;
    __syncthreads();
    float mu2 = (red[px * 2] + red[px * 2 + 1]) * (1.f / 256.f);
    float va2 = (red[512 + px * 2] + red[512 + px * 2 + 1]) * (1.f / 256.f);
    float rstd2 = rsqrtf(va2 - mu2 * mu2 + 1e-5f);

    float* op = out + ((size_t)(b * CC) + hf * 128) * HW + (size_t)row * WWD + px;
    for (int i = 0; i < 128; i++) {
        int c = hf * 128 + i;
        float v = yrow[i];
        op[(size_t)i * HW] = v + (v - mu2) * rstd2 * ln2w[c] + ln2b[c];
    }
}

// ------------------------------------------------------------------
extern "C" void kernel_launch(void* const* d_in, const int* in_sizes, int n_in,
                              void* d_out, int out_size)
{
    const float* x    = (const float*)d_in[0];
    const float* Wq   = (const float*)d_in[1];
    const float* Wk   = (const float*)d_in[2];
    const float* Wv   = (const float*)d_in[3];
    const float* gam  = (const float*)d_in[4];
    const float* W1   = (const float*)d_in[5];
    const float* b1   = (const float*)d_in[6];
    const float* W2   = (const float*)d_in[7];
    const float* b2   = (const float*)d_in[8];
    const float* ln1w = (const float*)d_in[9];
    const float* ln1b = (const float*)d_in[10];
    const float* ln2w = (const float*)d_in[11];
    const float* ln2b = (const float*)d_in[12];
    float* out = (float*)d_out;

    cudaFuncSetAttribute(attn_fused_kernel, cudaFuncAttributeMaxDynamicSharedMemorySize, AT_SMEM);
    cudaFuncSetAttribute(ffn_mma_kernel, cudaFuncAttributeMaxDynamicSharedMemorySize, FFN_SMEM_BYTES);

    attn_fused_kernel<<<NWIN, 256, AT_SMEM>>>(x, Wq, Wk, Wv, gam);
    ffn_mma_kernel<<<BQ * HH, 256, FFN_SMEM_BYTES>>>(W1, b1, W2, b2, ln1w, ln1b, ln2w, ln2b, out);
}

// round 13
// speedup vs baseline: 1.1239x; 1.1239x over previous
#include <cuda_runtime.h>
#include <cuda_bf16.h>
#include <math.h>
#include <stdint.h>

#define BQ   8
#define CC   256
#define HH   128
#define WWD  128
#define GG   16
#define NWIN 512
#define NT   256
#define C8   32
#define FF   1024
#define HW   16384

// ---------------- device scratch ----------------
__device__ __align__(128) float g_xa[(size_t)BQ * CC * HH * WWD];

// ================= helpers =================
__device__ __forceinline__ uint32_t smem_u32(const void* p) {
    uint32_t a;
    asm("{ .reg .u64 t; cvta.to.shared.u64 t, %1; cvt.u32.u64 %0, t; }" : "=r"(a) : "l"(p));
    return a;
}
__device__ __forceinline__ void mma_tf32(float* d, float a0, float a1, float a2, float a3,
                                         float b0, float b1) {
    asm volatile(
        "mma.sync.aligned.m16n8k8.row.col.f32.tf32.tf32.f32 "
        "{%0,%1,%2,%3}, {%4,%5,%6,%7}, {%8,%9}, {%0,%1,%2,%3};"
        : "+f"(d[0]), "+f"(d[1]), "+f"(d[2]), "+f"(d[3])
        : "r"(__float_as_uint(a0)), "r"(__float_as_uint(a1)),
          "r"(__float_as_uint(a2)), "r"(__float_as_uint(a3)),
          "r"(__float_as_uint(b0)), "r"(__float_as_uint(b1)));
}
__device__ __forceinline__ void mma_bf16(float* d, uint32_t a0, uint32_t a1, uint32_t a2, uint32_t a3,
                                         uint32_t b0, uint32_t b1) {
    asm volatile(
        "mma.sync.aligned.m16n8k16.row.col.f32.bf16.bf16.f32 "
        "{%0,%1,%2,%3}, {%4,%5,%6,%7}, {%8,%9}, {%0,%1,%2,%3};"
        : "+f"(d[0]), "+f"(d[1]), "+f"(d[2]), "+f"(d[3])
        : "r"(a0), "r"(a1), "r"(a2), "r"(a3), "r"(b0), "r"(b1));
}
__device__ __forceinline__ uint32_t packbf(float a, float b) {
    __nv_bfloat162 h = __float22bfloat162_rn(make_float2(a, b));
    return *(uint32_t*)&h;
}
#define CP16(dst, src) asm volatile("cp.async.cg.shared.global [%0], [%1], 16;" :: "r"(dst), "l"(src))
#define CP_COMMIT()    asm volatile("cp.async.commit_group;" ::: "memory")
#define CP_WAIT1()     asm volatile("cp.async.wait_group 1;" ::: "memory")
#define CP_WAIT0()     asm volatile("cp.async.wait_group 0;" ::: "memory")

__device__ __forceinline__ float gelu_exact(float v) { return v * normcdff(v); }

// ------------------------------------------------------------------
// Kernel 1: FUSED window attention (R11: max-free softmax, 4 bar/mq)
// ------------------------------------------------------------------
#define AT_XS  0
#define AT_ES  135168
#define AT_TS  135168
#define AT_WQS 135168
#define AT_WKS (135168 + 16896)
#define AT_QS  168960
#define AT_KS  187392
#define AT_RED 205824
#define AT_SMEM 206848

__global__ void __launch_bounds__(256) attn_fused_kernel(const float* __restrict__ x,
                                                         const float* __restrict__ Wq,
                                                         const float* __restrict__ Wk,
                                                         const float* __restrict__ Wv,
                                                         const float* __restrict__ gamma)
{
    extern __shared__ __align__(16) char sp[];
    const int tid = threadIdx.x, lane = tid & 31, wp = tid >> 5;
    const int g = lane >> 2, t = lane & 3;
    const int w = blockIdx.x, b = w >> 6, ih = (w >> 3) & 7, iw = w & 7;

    const float* xw = x + (size_t)b * CC * HW + ih * GG * WWD + iw * GG;
    const float gam = __ldg(gamma);

    for (int it = 0; it < 128; it++) {
        int i = it * 256 + tid;
        int c = i >> 7, pr = i & 127;
        int n = pr * 2, gy = n >> 4, gx = n & 15;
        float2 v = *(const float2*)(xw + (size_t)c * HW + gy * WWD + gx);
        *(uint32_t*)(sp + AT_XS + c * 528 + n * 2) = packbf(v.x, v.y);
    }
    for (int it = 0; it < 16; it++) {
        int i = it * 256 + tid;
        int o = i >> 7, cp2 = (i & 127) * 2;
        float2 q2 = *(const float2*)(Wq + (size_t)o * CC + cp2);
        *(uint32_t*)(sp + AT_WQS + o * 528 + cp2 * 2) = packbf(q2.x, q2.y);
        float2 k2 = *(const float2*)(Wk + (size_t)o * CC + cp2);
        *(uint32_t*)(sp + AT_WKS + o * 528 + cp2 * 2) = packbf(k2.x, k2.y);
    }
    __syncthreads();

    {
        const int n0 = wp * 32;
        const uint16_t* xb16 = (const uint16_t*)(sp + AT_XS);
        float Dq[2][4][4], Dk[2][4][4];
#pragma unroll
        for (int mi = 0; mi < 2; mi++)
#pragma unroll
            for (int nf = 0; nf < 4; nf++)
#pragma unroll
                for (int r = 0; r < 4; r++) { Dq[mi][nf][r] = 0.f; Dk[mi][nf][r] = 0.f; }

#pragma unroll 4
        for (int ks = 0; ks < 16; ks++) {
            uint32_t Aq[2][4], Ak[2][4];
#pragma unroll
            for (int mi = 0; mi < 2; mi++) {
                const char* aq = sp + AT_WQS + (mi * 16 + g) * 528 + ks * 32 + t * 4;
                Aq[mi][0] = *(const uint32_t*)aq;
                Aq[mi][1] = *(const uint32_t*)(aq + 8 * 528);
                Aq[mi][2] = *(const uint32_t*)(aq + 16);
                Aq[mi][3] = *(const uint32_t*)(aq + 8 * 528 + 16);
                const char* ak = sp + AT_WKS + (mi * 16 + g) * 528 + ks * 32 + t * 4;
                Ak[mi][0] = *(const uint32_t*)ak;
                Ak[mi][1] = *(const uint32_t*)(ak + 8 * 528);
                Ak[mi][2] = *(const uint32_t*)(ak + 16);
                Ak[mi][3] = *(const uint32_t*)(ak + 8 * 528 + 16);
            }
            int c0k = ks * 16 + 2 * t;
#pragma unroll
            for (int nf = 0; nf < 4; nf++) {
                int tok = n0 + nf * 8 + g;
                uint32_t b0 = (uint32_t)xb16[c0k * 264 + tok]
                            | ((uint32_t)xb16[(c0k + 1) * 264 + tok] << 16);
                uint32_t b1 = (uint32_t)xb16[(c0k + 8) * 264 + tok]
                            | ((uint32_t)xb16[(c0k + 9) * 264 + tok] << 16);
#pragma unroll
                for (int mi = 0; mi < 2; mi++) {
                    mma_bf16(Dq[mi][nf], Aq[mi][0], Aq[mi][1], Aq[mi][2], Aq[mi][3], b0, b1);
                    mma_bf16(Dk[mi][nf], Ak[mi][0], Ak[mi][1], Ak[mi][2], Ak[mi][3], b0, b1);
                }
            }
        }
        __nv_bfloat16* qs = (__nv_bfloat16*)(sp + AT_QS);
        __nv_bfloat16* ksm = (__nv_bfloat16*)(sp + AT_KS);
#pragma unroll
        for (int mi = 0; mi < 2; mi++)
#pragma unroll
            for (int nf = 0; nf < 4; nf++) {
                int o_lo = mi * 16 + g, o_hi = o_lo + 8;
                int tok = n0 + nf * 8 + 2 * t;
                qs[tok * 36 + o_lo] = __float2bfloat16(Dq[mi][nf][0]);
                qs[(tok + 1) * 36 + o_lo] = __float2bfloat16(Dq[mi][nf][1]);
                qs[tok * 36 + o_hi] = __float2bfloat16(Dq[mi][nf][2]);
                qs[(tok + 1) * 36 + o_hi] = __float2bfloat16(Dq[mi][nf][3]);
                ksm[tok * 36 + o_lo] = __float2bfloat16(Dk[mi][nf][0]);
                ksm[(tok + 1) * 36 + o_lo] = __float2bfloat16(Dk[mi][nf][1]);
                ksm[tok * 36 + o_hi] = __float2bfloat16(Dk[mi][nf][2]);
                ksm[(tok + 1) * 36 + o_hi] = __float2bfloat16(Dk[mi][nf][3]);
            }
    }

    const int wm = wp >> 2, wn = wp & 3;
    const int m0s = wm * 32, n0s = wn * 64;
    const int c0 = wp * 32;
    float* red = (float*)(sp + AT_RED);

    for (int mq = 0; mq < 4; mq++) {
        const int mqb = mq * 64;
        __syncthreads();

        float S[2][8][4];
#pragma unroll
        for (int mi = 0; mi < 2; mi++)
#pragma unroll
            for (int ni = 0; ni < 8; ni++)
#pragma unroll
                for (int r = 0; r < 4; r++) S[mi][ni][r] = 0.f;

#pragma unroll
        for (int ks = 0; ks < 2; ks++) {
            uint32_t A[2][4];
#pragma unroll
            for (int mi = 0; mi < 2; mi++) {
                const char* ab = sp + AT_QS + (mqb + m0s + mi * 16 + g) * 72 + ks * 32 + t * 4;
                A[mi][0] = *(const uint32_t*)ab;
                A[mi][1] = *(const uint32_t*)(ab + 8 * 72);
                A[mi][2] = *(const uint32_t*)(ab + 16);
                A[mi][3] = *(const uint32_t*)(ab + 8 * 72 + 16);
            }
#pragma unroll
            for (int ni = 0; ni < 8; ni++) {
                const char* bb = sp + AT_KS + (n0s + ni * 8 + g) * 72 + ks * 32 + t * 4;
                uint32_t b0 = *(const uint32_t*)bb;
                uint32_t b1 = *(const uint32_t*)(bb + 16);
                mma_bf16(S[0][ni], A[0][0], A[0][1], A[0][2], A[0][3], b0, b1);
                mma_bf16(S[1][ni], A[1][0], A[1][1], A[1][2], A[1][3], b0, b1);
            }
        }

        float sum[2][2];
#pragma unroll
        for (int mi = 0; mi < 2; mi++) { sum[mi][0] = 0.f; sum[mi][1] = 0.f; }
#pragma unroll
        for (int mi = 0; mi < 2; mi++) {
#pragma unroll
            for (int ni = 0; ni < 8; ni++) {
                float e0 = __expf(S[mi][ni][0]);
                float e1 = __expf(S[mi][ni][1]);
                float e2 = __expf(S[mi][ni][2]);
                float e3 = __expf(S[mi][ni][3]);
                sum[mi][0] += e0 + e1;
                sum[mi][1] += e2 + e3;
                int ncol = (n0s + ni * 8 + 2 * t) * 2;
                *(uint32_t*)(sp + AT_ES + (m0s + mi * 16 + g) * 528 + ncol) = packbf(e0, e1);
                *(uint32_t*)(sp + AT_ES + (m0s + mi * 16 + g + 8) * 528 + ncol) = packbf(e2, e3);
            }
#pragma unroll
            for (int h = 0; h < 2; h++) {
                sum[mi][h] += __shfl_xor_sync(0xffffffff, sum[mi][h], 1);
                sum[mi][h] += __shfl_xor_sync(0xffffffff, sum[mi][h], 2);
            }
        }
        if (t == 0) {
#pragma unroll
            for (int mi = 0; mi < 2; mi++)
#pragma unroll
                for (int h = 0; h < 2; h++)
                    red[wn * 64 + m0s + mi * 16 + g + 8 * h] = sum[mi][h];
        }
        __syncthreads();

        float zrv[4][2];
#pragma unroll
        for (int mi = 0; mi < 4; mi++)
#pragma unroll
            for (int h = 0; h < 2; h++) {
                int row = mi * 16 + g + 8 * h;
                zrv[mi][h] = gam / (red[row] + red[64 + row] + red[128 + row] + red[192 + row]);
            }

        float Dt[4][4][4];
#pragma unroll
        for (int mi = 0; mi < 4; mi++)
#pragma unroll
            for (int ci = 0; ci < 4; ci++)
#pragma unroll
                for (int r = 0; r < 4; r++) Dt[mi][ci][r] = 0.f;

#pragma unroll 4
        for (int kk = 0; kk < 16; kk++) {
            uint32_t A[4][4];
#pragma unroll
            for (int mi = 0; mi < 4; mi++) {
                const char* ab = sp + AT_ES + (mi * 16 + g) * 528 + kk * 32 + t * 4;
                A[mi][0] = *(const uint32_t*)ab;
                A[mi][1] = *(const uint32_t*)(ab + 8 * 528);
                A[mi][2] = *(const uint32_t*)(ab + 16);
                A[mi][3] = *(const uint32_t*)(ab + 8 * 528 + 16);
            }
#pragma unroll
            for (int ci = 0; ci < 4; ci++) {
                const char* bb = sp + AT_XS + (c0 + ci * 8 + g) * 528 + kk * 32 + t * 4;
                uint32_t b0 = *(const uint32_t*)bb;
                uint32_t b1 = *(const uint32_t*)(bb + 16);
#pragma unroll
                for (int mi = 0; mi < 4; mi++)
                    mma_bf16(Dt[mi][ci], A[mi][0], A[mi][1], A[mi][2], A[mi][3], b0, b1);
            }
        }
        __syncthreads();
#pragma unroll
        for (int mi = 0; mi < 4; mi++)
#pragma unroll
            for (int ci = 0; ci < 4; ci++) {
                int ccol = (c0 + ci * 8 + 2 * t) * 2;
                *(uint32_t*)(sp + AT_TS + (mi * 16 + g) * 528 + ccol) = packbf(Dt[mi][ci][0], Dt[mi][ci][1]);
                *(uint32_t*)(sp + AT_TS + (mi * 16 + g + 8) * 528 + ccol) = packbf(Dt[mi][ci][2], Dt[mi][ci][3]);
            }
        __syncthreads();

        float Do[4][4][4];
#pragma unroll
        for (int mi = 0; mi < 4; mi++)
#pragma unroll
            for (int cj = 0; cj < 4; cj++)
#pragma unroll
                for (int r = 0; r < 4; r++) Do[mi][cj][r] = 0.f;

#pragma unroll 4
        for (int kk = 0; kk < 16; kk++) {
            uint32_t A[4][4];
#pragma unroll
            for (int mi = 0; mi < 4; mi++) {
                const char* ab = sp + AT_TS + (mi * 16 + g) * 528 + kk * 32 + t * 4;
                A[mi][0] = *(const uint32_t*)ab;
                A[mi][1] = *(const uint32_t*)(ab + 8 * 528);
                A[mi][2] = *(const uint32_t*)(ab + 16);
                A[mi][3] = *(const uint32_t*)(ab + 8 * 528 + 16);
            }
#pragma unroll
            for (int cj = 0; cj < 4; cj++) {
                const float* wv = Wv + (size_t)(c0 + cj * 8 + g) * CC + kk * 16 + 2 * t;
                float2 f0 = *(const float2*)wv;
                float2 f1 = *(const float2*)(wv + 8);
                uint32_t b0 = packbf(f0.x, f0.y);
                uint32_t b1 = packbf(f1.x, f1.y);
#pragma unroll
                for (int mi = 0; mi < 4; mi++)
                    mma_bf16(Do[mi][cj], A[mi][0], A[mi][1], A[mi][2], A[mi][3], b0, b1);
            }
        }

        {
            float* xab = g_xa + (size_t)b * CC * HW + ih * GG * WWD + iw * GG;
#pragma unroll
            for (int mi = 0; mi < 4; mi++) {
                float z0 = zrv[mi][0], z1 = zrv[mi][1];
                int tok0 = mqb + mi * 16 + g, tok1 = tok0 + 8;
                int p0 = (tok0 >> 4) * WWD + (tok0 & 15);
                int p1 = (tok1 >> 4) * WWD + (tok1 & 15);
#pragma unroll
                for (int cj = 0; cj < 4; cj++) {
                    int co = c0 + cj * 8 + 2 * t;
                    size_t o00 = (size_t)co * HW + p0;
                    size_t o01 = (size_t)(co + 1) * HW + p0;
                    size_t o10 = (size_t)co * HW + p1;
                    size_t o11 = (size_t)(co + 1) * HW + p1;
                    xab[o00] = Do[mi][cj][0] * z0 + xw[o00];
                    xab[o01] = Do[mi][cj][1] * z0 + xw[o01];
                    xab[o10] = Do[mi][cj][2] * z1 + xw[o10];
                    xab[o11] = Do[mi][cj][3] * z1 + xw[o11];
                }
            }
        }
    }
}

// ------------------------------------------------------------------
// Kernel 2: tf32 FFN (R8 pipelined) — xs staged via cp.async raw fp32
// (bundled into the W1(0) group), no explicit tf32 converts (HW
// truncates fp32 operands; same path the weights already use).
// ------------------------------------------------------------------
#define XS_OFF 0
#define HS_OFF 33792
#define W1_OFF 38016
#define W2_OFF 46336
#define FFN_SMEM_FLOATS 55552
#define FFN_SMEM_BYTES (FFN_SMEM_FLOATS * 4)

__global__ void __launch_bounds__(256) ffn_mma_kernel(const float* __restrict__ W1,
                                                      const float* __restrict__ b1,
                                                      const float* __restrict__ W2,
                                                      const float* __restrict__ b2,
                                                      const float* __restrict__ ln1w,
                                                      const float* __restrict__ ln1b,
                                                      const float* __restrict__ ln2w,
                                                      const float* __restrict__ ln2b,
                                                      float* __restrict__ out)
{
    extern __shared__ __align__(16) float sm[];
    float* xs  = sm + XS_OFF;
    float* hs  = sm + HS_OFF;
    float* w1s = sm + W1_OFF;
    float* w2s = sm + W2_OFF;
    const uint32_t xsu = smem_u32(xs);
    const uint32_t w1u = smem_u32(w1s);
    const uint32_t w2u = smem_u32(w2s);

    const int tid = threadIdx.x, lane = tid & 31, wp = tid >> 5;
    const int g = lane >> 2, t = lane & 3;
    const int blk = blockIdx.x, b = blk >> 7, row = blk & 127;

    const int fr0 = (wp >> 2) * 16;
    const int px0 = (wp & 3) * 32;
    const int pxm0 = (wp & 3) * 32;
    const int c0w = (wp >> 2) * 128;

    // ---- group 1: W1(0) + xs (raw fp32, async) ----
    for (int j = 0; j < 8; j++) {
        int id = tid + j * 256;
        int f = id >> 6, seg = id & 63;
        CP16(w1u + (uint32_t)(f * 260 + seg * 4) * 4u, W1 + (size_t)f * CC + seg * 4);
    }
    {
        // xs [256c][132px]: 256 rows x 32 chunks(4px) = 8192 chunks
        const float* xab = g_xa + (size_t)b * CC * HW + (size_t)row * WWD;
#pragma unroll 4
        for (int j = 0; j < 32; j++) {
            int id = tid + j * 256;
            int c = id >> 5, s = id & 31;     // chunk s: px 4s..4s+3
            CP16(xsu + (uint32_t)(c * 132 + s * 4) * 4u, xab + (size_t)c * HW + s * 4);
        }
    }
    CP_COMMIT();
    // ---- group 2: W2(0) ----
    for (int j = 0; j < 8; j++) {
        int id = tid + j * 256;
        int c = id >> 3, seg = id & 7;
        CP16(w2u + (uint32_t)(c * 36 + seg * 4) * 4u, W2 + (size_t)c * FF + seg * 4);
    }
    CP_COMMIT();

    float yacc[2][16][4];
#pragma unroll
    for (int mf = 0; mf < 2; mf++)
#pragma unroll
        for (int nf = 0; nf < 16; nf++)
#pragma unroll
            for (int r = 0; r < 4; r++) yacc[mf][nf][r] = 0.f;

    const float* wr0 = w1s + (fr0 + g) * 260;
    const float* wr1 = wr0 + 8 * 260;
    const float* xb0 = xs + t * 132 + px0 + g;

    float d1[4][4];
#pragma unroll
    for (int nf = 0; nf < 4; nf++)
#pragma unroll
        for (int r = 0; r < 4; r++) d1[nf][r] = 0.f;

    CP_WAIT1();                // W1(0) + xs landed (W2(0) in flight)
    __syncthreads();
#pragma unroll 8
    for (int ks = 0; ks < 32; ks++) {
        int k = ks * 8;
        float a0 = wr0[k + t], a1 = wr1[k + t];
        float a2 = wr0[k + t + 4], a3 = wr1[k + t + 4];
        const float* xk = xb0 + k * 132;
#pragma unroll
        for (int nf = 0; nf < 4; nf++)
            mma_tf32(d1[nf], a0, a1, a2, a3, xk[nf * 8], xk[4 * 132 + nf * 8]);
    }
    __syncthreads();
    {
        const float* src = W1 + (size_t)32 * CC;
        for (int j = 0; j < 8; j++) {
            int id = tid + j * 256;
            int f = id >> 6, seg = id & 63;
            CP16(w1u + (uint32_t)(f * 260 + seg * 4) * 4u, src + (size_t)f * CC + seg * 4);
        }
        CP_COMMIT();
    }

    for (int ft = 0; ft < 32; ft++) {
        const int ftb = ft * 32;

        {
            float b1a = __ldg(&b1[ftb + fr0 + g]);
            float b1b = __ldg(&b1[ftb + fr0 + g + 8]);
#pragma unroll
            for (int nf = 0; nf < 4; nf++) {
                int px = px0 + nf * 8 + 2 * t;
                float2 v01 = make_float2(gelu_exact(d1[nf][0] + b1a),
                                         gelu_exact(d1[nf][1] + b1a));
                float2 v23 = make_float2(gelu_exact(d1[nf][2] + b1b),
                                         gelu_exact(d1[nf][3] + b1b));
                *(float2*)&hs[(fr0 + g) * 132 + px] = v01;
                *(float2*)&hs[(fr0 + g + 8) * 132 + px] = v23;
            }
        }
        CP_WAIT0();
        __syncthreads();

        float d1n[4][4];
#pragma unroll
        for (int nf = 0; nf < 4; nf++)
#pragma unroll
            for (int r = 0; r < 4; r++) d1n[nf][r] = 0.f;

        const bool more = (ft < 31);
#pragma unroll
        for (int ks2 = 0; ks2 < 4; ks2++) {
            const int k2 = ks2 * 8;
            float am[2][4];
#pragma unroll
            for (int mf = 0; mf < 2; mf++) {
                const float* hb = hs + (k2 + t) * 132 + pxm0 + 16 * mf + g;
                am[mf][0] = hb[0];
                am[mf][1] = hb[8];
                am[mf][2] = hb[4 * 132];
                am[mf][3] = hb[4 * 132 + 8];
            }
#pragma unroll
            for (int jj = 0; jj < 8; jj++) {
                if (more) {
                    int k = (ks2 * 8 + jj) * 8;
                    float a0 = wr0[k + t], a1 = wr1[k + t];
                    float a2 = wr0[k + t + 4], a3 = wr1[k + t + 4];
                    const float* xk = xb0 + k * 132;
#pragma unroll
                    for (int nf = 0; nf < 4; nf++)
                        mma_tf32(d1n[nf], a0, a1, a2, a3, xk[nf * 8], xk[4 * 132 + nf * 8]);
                }
#pragma unroll
                for (int u = 0; u < 2; u++) {
                    int nf = jj * 2 + u;
                    const float* wb = w2s + (c0w + nf * 8 + g) * 36 + k2 + t;
                    float b0 = wb[0], b1v = wb[4];
                    mma_tf32(yacc[0][nf], am[0][0], am[0][1], am[0][2], am[0][3], b0, b1v);
                    mma_tf32(yacc[1][nf], am[1][0], am[1][1], am[1][2], am[1][3], b0, b1v);
                }
            }
        }
        __syncthreads();

        if (ft < 31) {
            const float* src2 = W2 + (size_t)(ftb + 32);
            for (int j = 0; j < 8; j++) {
                int id = tid + j * 256;
                int c = id >> 3, seg = id & 7;
                CP16(w2u + (uint32_t)(c * 36 + seg * 4) * 4u, src2 + (size_t)c * FF + seg * 4);
            }
            if (ft < 30) {
                const float* src1 = W1 + (size_t)(ftb + 64) * CC;
                for (int j = 0; j < 8; j++) {
                    int id = tid + j * 256;
                    int f = id >> 6, seg = id & 63;
                    CP16(w1u + (uint32_t)(f * 260 + seg * 4) * 4u, src1 + (size_t)f * CC + seg * 4);
                }
            }
            CP_COMMIT();
        }

#pragma unroll
        for (int nf = 0; nf < 4; nf++)
#pragma unroll
            for (int r = 0; r < 4; r++) d1[nf][r] = d1n[nf][r];
    }
    __syncthreads();

    float* ys = sm;
#pragma unroll
    for (int nf = 0; nf < 16; nf++) {
        int c = c0w + nf * 8 + 2 * t;
        float b2a = __ldg(&b2[c]);
        float b2b = __ldg(&b2[c + 1]);
#pragma unroll
        for (int mf = 0; mf < 2; mf++) {
            int pxr = pxm0 + 16 * mf + g;
            *(float2*)&ys[pxr * 260 + c] =
                make_float2(yacc[mf][nf][0] + b2a, yacc[mf][nf][1] + b2b);
            *(float2*)&ys[(pxr + 8) * 260 + c] =
                make_float2(yacc[mf][nf][2] + b2a, yacc[mf][nf][3] + b2b);
        }
    }
    __syncthreads();

    int px = tid >> 1, hf = tid & 1;
    float* yrow = ys + px * 260 + hf * 128;
    float* red = hs;

    float s1 = 0.f, s2 = 0.f;
#pragma unroll 8
    for (int i = 0; i < 128; i += 4) {
        float4 v = *(float4*)&yrow[i];
        s1 += v.x + v.y + v.z + v.w;
        s2 += v.x * v.x + v.y * v.y + v.z * v.z + v.w * v.w;
    }
    red[tid] = s1; red[512 + tid] = s2;
    __syncthreads();
    float mu = (red[px * 2] + red[px * 2 + 1]) * (1.f / 256.f);
    float va = (red[512 + px * 2] + red[512 + px * 2 + 1]) * (1.f / 256.f);
    float rstd = rsqrtf(va - mu * mu + 1e-5f);

    const float* xsrc = g_xa + ((size_t)(b * CC) + hf * 128) * HW + (size_t)row * WWD + px;
    float t1 = 0.f, t2 = 0.f;
    for (int i = 0; i < 128; i++) {
        int c = hf * 128 + i;
        float x2v = xsrc[(size_t)i * HW] + (yrow[i] - mu) * rstd * ln1w[c] + ln1b[c];
        yrow[i] = x2v;
        t1 += x2v; t2 += x2v * x2v;
    }
    __syncthreads();
    red[tid] = t1; red[512 + tid] = t2;
    __syncthreads();
    float mu2 = (red[px * 2] + red[px * 2 + 1]) * (1.f / 256.f);
    float va2 = (red[512 + px * 2] + red[512 + px * 2 + 1]) * (1.f / 256.f);
    float rstd2 = rsqrtf(va2 - mu2 * mu2 + 1e-5f);

    float* op = out + ((size_t)(b * CC) + hf * 128) * HW + (size_t)row * WWD + px;
    for (int i = 0; i < 128; i++) {
        int c = hf * 128 + i;
        float v = yrow[i];
        op[(size_t)i * HW] = v + (v - mu2) * rstd2 * ln2w[c] + ln2b[c];
    }
}

// ------------------------------------------------------------------
extern "C" void kernel_launch(void* const* d_in, const int* in_sizes, int n_in,
                              void* d_out, int out_size)
{
    const float* x    = (const float*)d_in[0];
    const float* Wq   = (const float*)d_in[1];
    const float* Wk   = (const float*)d_in[2];
    const float* Wv   = (const float*)d_in[3];
    const float* gam  = (const float*)d_in[4];
    const float* W1   = (const float*)d_in[5];
    const float* b1   = (const float*)d_in[6];
    const float* W2   = (const float*)d_in[7];
    const float* b2   = (const float*)d_in[8];
    const float* ln1w = (const float*)d_in[9];
    const float* ln1b = (const float*)d_in[10];
    const float* ln2w = (const float*)d_in[11];
    const float* ln2b = (const float*)d_in[12];
    float* out = (float*)d_out;

    cudaFuncSetAttribute(attn_fused_kernel, cudaFuncAttributeMaxDynamicSharedMemorySize, AT_SMEM);
    cudaFuncSetAttribute(ffn_mma_kernel, cudaFuncAttributeMaxDynamicSharedMemorySize, FFN_SMEM_BYTES);

    attn_fused_kernel<<<NWIN, 256, AT_SMEM>>>(x, Wq, Wk, Wv, gam);
    ffn_mma_kernel<<<BQ * HH, 256, FFN_SMEM_BYTES>>>(W1, b1, W2, b2, ln1w, ln1b, ln2w, ln2b, out);
}

// round 14
// speedup vs baseline: 1.1452x; 1.0189x over previous
#include <cuda_runtime.h>
#include <cuda_bf16.h>
#include <math.h>
#include <stdint.h>

#define BQ   8
#define CC   256
#define HH   128
#define WWD  128
#define GG   16
#define NWIN 512
#define NT   256
#define C8   32
#define FF   1024
#define HW   16384

// ---------------- device scratch ----------------
__device__ __align__(128) float g_xa[(size_t)BQ * CC * HH * WWD];
__device__ int g_flags[64];   // one per (batch, window-row)

// ================= helpers =================
__device__ __forceinline__ uint32_t smem_u32(const void* p) {
    uint32_t a;
    asm("{ .reg .u64 t; cvta.to.shared.u64 t, %1; cvt.u32.u64 %0, t; }" : "=r"(a) : "l"(p));
    return a;
}
__device__ __forceinline__ void mma_tf32(float* d, float a0, float a1, float a2, float a3,
                                         float b0, float b1) {
    asm volatile(
        "mma.sync.aligned.m16n8k8.row.col.f32.tf32.tf32.f32 "
        "{%0,%1,%2,%3}, {%4,%5,%6,%7}, {%8,%9}, {%0,%1,%2,%3};"
        : "+f"(d[0]), "+f"(d[1]), "+f"(d[2]), "+f"(d[3])
        : "r"(__float_as_uint(a0)), "r"(__float_as_uint(a1)),
          "r"(__float_as_uint(a2)), "r"(__float_as_uint(a3)),
          "r"(__float_as_uint(b0)), "r"(__float_as_uint(b1)));
}
__device__ __forceinline__ void mma_bf16(float* d, uint32_t a0, uint32_t a1, uint32_t a2, uint32_t a3,
                                         uint32_t b0, uint32_t b1) {
    asm volatile(
        "mma.sync.aligned.m16n8k16.row.col.f32.bf16.bf16.f32 "
        "{%0,%1,%2,%3}, {%4,%5,%6,%7}, {%8,%9}, {%0,%1,%2,%3};"
        : "+f"(d[0]), "+f"(d[1]), "+f"(d[2]), "+f"(d[3])
        : "r"(a0), "r"(a1), "r"(a2), "r"(a3), "r"(b0), "r"(b1));
}
__device__ __forceinline__ uint32_t packbf(float a, float b) {
    __nv_bfloat162 h = __float22bfloat162_rn(make_float2(a, b));
    return *(uint32_t*)&h;
}
#define CP16(dst, src) asm volatile("cp.async.cg.shared.global [%0], [%1], 16;" :: "r"(dst), "l"(src))
#define CP_COMMIT()    asm volatile("cp.async.commit_group;" ::: "memory")
#define CP_WAIT1()     asm volatile("cp.async.wait_group 1;" ::: "memory")
#define CP_WAIT0()     asm volatile("cp.async.wait_group 0;" ::: "memory")

__device__ __forceinline__ float gelu_exact(float v) { return v * normcdff(v); }

// smem layout constants
#define AT_XS  0
#define AT_ES  135168
#define AT_TS  135168
#define AT_WQS 135168
#define AT_WKS (135168 + 16896)
#define AT_QS  168960
#define AT_KS  187392
#define AT_RED 205824
#define AT_SMEM 206848

#define XS_OFF 0
#define HS_OFF 33792
#define W1_OFF 38016
#define W2_OFF 46336
#define FFN_SMEM_FLOATS 55552
#define FFN_SMEM_BYTES (FFN_SMEM_FLOATS * 4)

#define FUSED_SMEM (FFN_SMEM_BYTES > AT_SMEM ? FFN_SMEM_BYTES : AT_SMEM)

// ------------------------------------------------------------------
__global__ void reset_flags_kernel() {
    if (threadIdx.x < 64) g_flags[threadIdx.x] = 0;
}

// ------------------------------------------------------------------
// Attention body (R13, unchanged) + release-flag at end
// ------------------------------------------------------------------
__device__ void attn_body(const char* dummy,
                          const float* __restrict__ x,
                          const float* __restrict__ Wq,
                          const float* __restrict__ Wk,
                          const float* __restrict__ Wv,
                          const float* __restrict__ gamma,
                          char* sp, int w)
{
    const int tid = threadIdx.x, lane = tid & 31, wp = tid >> 5;
    const int g = lane >> 2, t = lane & 3;
    const int b = w >> 6, ih = (w >> 3) & 7, iw = w & 7;

    const float* xw = x + (size_t)b * CC * HW + ih * GG * WWD + iw * GG;
    const float gam = __ldg(gamma);

    for (int it = 0; it < 128; it++) {
        int i = it * 256 + tid;
        int c = i >> 7, pr = i & 127;
        int n = pr * 2, gy = n >> 4, gx = n & 15;
        float2 v = *(const float2*)(xw + (size_t)c * HW + gy * WWD + gx);
        *(uint32_t*)(sp + AT_XS + c * 528 + n * 2) = packbf(v.x, v.y);
    }
    for (int it = 0; it < 16; it++) {
        int i = it * 256 + tid;
        int o = i >> 7, cp2 = (i & 127) * 2;
        float2 q2 = *(const float2*)(Wq + (size_t)o * CC + cp2);
        *(uint32_t*)(sp + AT_WQS + o * 528 + cp2 * 2) = packbf(q2.x, q2.y);
        float2 k2 = *(const float2*)(Wk + (size_t)o * CC + cp2);
        *(uint32_t*)(sp + AT_WKS + o * 528 + cp2 * 2) = packbf(k2.x, k2.y);
    }
    __syncthreads();

    {
        const int n0 = wp * 32;
        const uint16_t* xb16 = (const uint16_t*)(sp + AT_XS);
        float Dq[2][4][4], Dk[2][4][4];
#pragma unroll
        for (int mi = 0; mi < 2; mi++)
#pragma unroll
            for (int nf = 0; nf < 4; nf++)
#pragma unroll
                for (int r = 0; r < 4; r++) { Dq[mi][nf][r] = 0.f; Dk[mi][nf][r] = 0.f; }

#pragma unroll 4
        for (int ks = 0; ks < 16; ks++) {
            uint32_t Aq[2][4], Ak[2][4];
#pragma unroll
            for (int mi = 0; mi < 2; mi++) {
                const char* aq = sp + AT_WQS + (mi * 16 + g) * 528 + ks * 32 + t * 4;
                Aq[mi][0] = *(const uint32_t*)aq;
                Aq[mi][1] = *(const uint32_t*)(aq + 8 * 528);
                Aq[mi][2] = *(const uint32_t*)(aq + 16);
                Aq[mi][3] = *(const uint32_t*)(aq + 8 * 528 + 16);
                const char* ak = sp + AT_WKS + (mi * 16 + g) * 528 + ks * 32 + t * 4;
                Ak[mi][0] = *(const uint32_t*)ak;
                Ak[mi][1] = *(const uint32_t*)(ak + 8 * 528);
                Ak[mi][2] = *(const uint32_t*)(ak + 16);
                Ak[mi][3] = *(const uint32_t*)(ak + 8 * 528 + 16);
            }
            int c0k = ks * 16 + 2 * t;
#pragma unroll
            for (int nf = 0; nf < 4; nf++) {
                int tok = n0 + nf * 8 + g;
                uint32_t b0 = (uint32_t)xb16[c0k * 264 + tok]
                            | ((uint32_t)xb16[(c0k + 1) * 264 + tok] << 16);
                uint32_t b1 = (uint32_t)xb16[(c0k + 8) * 264 + tok]
                            | ((uint32_t)xb16[(c0k + 9) * 264 + tok] << 16);
#pragma unroll
                for (int mi = 0; mi < 2; mi++) {
                    mma_bf16(Dq[mi][nf], Aq[mi][0], Aq[mi][1], Aq[mi][2], Aq[mi][3], b0, b1);
                    mma_bf16(Dk[mi][nf], Ak[mi][0], Ak[mi][1], Ak[mi][2], Ak[mi][3], b0, b1);
                }
            }
        }
        __nv_bfloat16* qs = (__nv_bfloat16*)(sp + AT_QS);
        __nv_bfloat16* ksm = (__nv_bfloat16*)(sp + AT_KS);
#pragma unroll
        for (int mi = 0; mi < 2; mi++)
#pragma unroll
            for (int nf = 0; nf < 4; nf++) {
                int o_lo = mi * 16 + g, o_hi = o_lo + 8;
                int tok = n0 + nf * 8 + 2 * t;
                qs[tok * 36 + o_lo] = __float2bfloat16(Dq[mi][nf][0]);
                qs[(tok + 1) * 36 + o_lo] = __float2bfloat16(Dq[mi][nf][1]);
                qs[tok * 36 + o_hi] = __float2bfloat16(Dq[mi][nf][2]);
                qs[(tok + 1) * 36 + o_hi] = __float2bfloat16(Dq[mi][nf][3]);
                ksm[tok * 36 + o_lo] = __float2bfloat16(Dk[mi][nf][0]);
                ksm[(tok + 1) * 36 + o_lo] = __float2bfloat16(Dk[mi][nf][1]);
                ksm[tok * 36 + o_hi] = __float2bfloat16(Dk[mi][nf][2]);
                ksm[(tok + 1) * 36 + o_hi] = __float2bfloat16(Dk[mi][nf][3]);
            }
    }

    const int wn = wp & 3;
    const int m0s = (wp >> 2) * 32, n0s = wn * 64;
    const int c0 = wp * 32;
    float* red = (float*)(sp + AT_RED);

    for (int mq = 0; mq < 4; mq++) {
        const int mqb = mq * 64;
        __syncthreads();

        float S[2][8][4];
#pragma unroll
        for (int mi = 0; mi < 2; mi++)
#pragma unroll
            for (int ni = 0; ni < 8; ni++)
#pragma unroll
                for (int r = 0; r < 4; r++) S[mi][ni][r] = 0.f;

#pragma unroll
        for (int ks = 0; ks < 2; ks++) {
            uint32_t A[2][4];
#pragma unroll
            for (int mi = 0; mi < 2; mi++) {
                const char* ab = sp + AT_QS + (mqb + m0s + mi * 16 + g) * 72 + ks * 32 + t * 4;
                A[mi][0] = *(const uint32_t*)ab;
                A[mi][1] = *(const uint32_t*)(ab + 8 * 72);
                A[mi][2] = *(const uint32_t*)(ab + 16);
                A[mi][3] = *(const uint32_t*)(ab + 8 * 72 + 16);
            }
#pragma unroll
            for (int ni = 0; ni < 8; ni++) {
                const char* bb = sp + AT_KS + (n0s + ni * 8 + g) * 72 + ks * 32 + t * 4;
                uint32_t b0 = *(const uint32_t*)bb;
                uint32_t b1 = *(const uint32_t*)(bb + 16);
                mma_bf16(S[0][ni], A[0][0], A[0][1], A[0][2], A[0][3], b0, b1);
                mma_bf16(S[1][ni], A[1][0], A[1][1], A[1][2], A[1][3], b0, b1);
            }
        }

        float sum[2][2];
#pragma unroll
        for (int mi = 0; mi < 2; mi++) { sum[mi][0] = 0.f; sum[mi][1] = 0.f; }
#pragma unroll
        for (int mi = 0; mi < 2; mi++) {
#pragma unroll
            for (int ni = 0; ni < 8; ni++) {
                float e0 = __expf(S[mi][ni][0]);
                float e1 = __expf(S[mi][ni][1]);
                float e2 = __expf(S[mi][ni][2]);
                float e3 = __expf(S[mi][ni][3]);
                sum[mi][0] += e0 + e1;
                sum[mi][1] += e2 + e3;
                int ncol = (n0s + ni * 8 + 2 * t) * 2;
                *(uint32_t*)(sp + AT_ES + (m0s + mi * 16 + g) * 528 + ncol) = packbf(e0, e1);
                *(uint32_t*)(sp + AT_ES + (m0s + mi * 16 + g + 8) * 528 + ncol) = packbf(e2, e3);
            }
#pragma unroll
            for (int h = 0; h < 2; h++) {
                sum[mi][h] += __shfl_xor_sync(0xffffffff, sum[mi][h], 1);
                sum[mi][h] += __shfl_xor_sync(0xffffffff, sum[mi][h], 2);
            }
        }
        if (t == 0) {
#pragma unroll
            for (int mi = 0; mi < 2; mi++)
#pragma unroll
                for (int h = 0; h < 2; h++)
                    red[wn * 64 + m0s + mi * 16 + g + 8 * h] = sum[mi][h];
        }
        __syncthreads();

        float zrv[4][2];
#pragma unroll
        for (int mi = 0; mi < 4; mi++)
#pragma unroll
            for (int h = 0; h < 2; h++) {
                int row = mi * 16 + g + 8 * h;
                zrv[mi][h] = gam / (red[row] + red[64 + row] + red[128 + row] + red[192 + row]);
            }

        float Dt[4][4][4];
#pragma unroll
        for (int mi = 0; mi < 4; mi++)
#pragma unroll
            for (int ci = 0; ci < 4; ci++)
#pragma unroll
                for (int r = 0; r < 4; r++) Dt[mi][ci][r] = 0.f;

#pragma unroll 4
        for (int kk = 0; kk < 16; kk++) {
            uint32_t A[4][4];
#pragma unroll
            for (int mi = 0; mi < 4; mi++) {
                const char* ab = sp + AT_ES + (mi * 16 + g) * 528 + kk * 32 + t * 4;
                A[mi][0] = *(const uint32_t*)ab;
                A[mi][1] = *(const uint32_t*)(ab + 8 * 528);
                A[mi][2] = *(const uint32_t*)(ab + 16);
                A[mi][3] = *(const uint32_t*)(ab + 8 * 528 + 16);
            }
#pragma unroll
            for (int ci = 0; ci < 4; ci++) {
                const char* bb = sp + AT_XS + (c0 + ci * 8 + g) * 528 + kk * 32 + t * 4;
                uint32_t b0 = *(const uint32_t*)bb;
                uint32_t b1 = *(const uint32_t*)(bb + 16);
#pragma unroll
                for (int mi = 0; mi < 4; mi++)
                    mma_bf16(Dt[mi][ci], A[mi][0], A[mi][1], A[mi][2], A[mi][3], b0, b1);
            }
        }
        __syncthreads();
#pragma unroll
        for (int mi = 0; mi < 4; mi++)
#pragma unroll
            for (int ci = 0; ci < 4; ci++) {
                int ccol = (c0 + ci * 8 + 2 * t) * 2;
                *(uint32_t*)(sp + AT_TS + (mi * 16 + g) * 528 + ccol) = packbf(Dt[mi][ci][0], Dt[mi][ci][1]);
                *(uint32_t*)(sp + AT_TS + (mi * 16 + g + 8) * 528 + ccol) = packbf(Dt[mi][ci][2], Dt[mi][ci][3]);
            }
        __syncthreads();

        float Do[4][4][4];
#pragma unroll
        for (int mi = 0; mi < 4; mi++)
#pragma unroll
            for (int cj = 0; cj < 4; cj++)
#pragma unroll
                for (int r = 0; r < 4; r++) Do[mi][cj][r] = 0.f;

#pragma unroll 4
        for (int kk = 0; kk < 16; kk++) {
            uint32_t A[4][4];
#pragma unroll
            for (int mi = 0; mi < 4; mi++) {
                const char* ab = sp + AT_TS + (mi * 16 + g) * 528 + kk * 32 + t * 4;
                A[mi][0] = *(const uint32_t*)ab;
                A[mi][1] = *(const uint32_t*)(ab + 8 * 528);
                A[mi][2] = *(const uint32_t*)(ab + 16);
                A[mi][3] = *(const uint32_t*)(ab + 8 * 528 + 16);
            }
#pragma unroll
            for (int cj = 0; cj < 4; cj++) {
                const float* wv = Wv + (size_t)(c0 + cj * 8 + g) * CC + kk * 16 + 2 * t;
                float2 f0 = *(const float2*)wv;
                float2 f1 = *(const float2*)(wv + 8);
                uint32_t b0 = packbf(f0.x, f0.y);
                uint32_t b1 = packbf(f1.x, f1.y);
#pragma unroll
                for (int mi = 0; mi < 4; mi++)
                    mma_bf16(Do[mi][cj], A[mi][0], A[mi][1], A[mi][2], A[mi][3], b0, b1);
            }
        }

        {
            float* xab = g_xa + (size_t)b * CC * HW + ih * GG * WWD + iw * GG;
#pragma unroll
            for (int mi = 0; mi < 4; mi++) {
                float z0 = zrv[mi][0], z1 = zrv[mi][1];
                int tok0 = mqb + mi * 16 + g, tok1 = tok0 + 8;
                int p0 = (tok0 >> 4) * WWD + (tok0 & 15);
                int p1 = (tok1 >> 4) * WWD + (tok1 & 15);
#pragma unroll
                for (int cj = 0; cj < 4; cj++) {
                    int co = c0 + cj * 8 + 2 * t;
                    size_t o00 = (size_t)co * HW + p0;
                    size_t o01 = (size_t)(co + 1) * HW + p0;
                    size_t o10 = (size_t)co * HW + p1;
                    size_t o11 = (size_t)(co + 1) * HW + p1;
                    xab[o00] = Do[mi][cj][0] * z0 + xw[o00];
                    xab[o01] = Do[mi][cj][1] * z0 + xw[o01];
                    xab[o10] = Do[mi][cj][2] * z1 + xw[o10];
                    xab[o11] = Do[mi][cj][3] * z1 + xw[o11];
                }
            }
        }
    }

    // ---- release: publish this window to FFN consumers ----
    __threadfence();
    __syncthreads();
    if (tid == 0) atomicAdd(&g_flags[b * 8 + ih], 1);
}

// ------------------------------------------------------------------
// FFN body (R13, unchanged except acquire-spin at entry)
// ------------------------------------------------------------------
__device__ void ffn_body(const float* __restrict__ W1,
                         const float* __restrict__ b1,
                         const float* __restrict__ W2,
                         const float* __restrict__ b2,
                         const float* __restrict__ ln1w,
                         const float* __restrict__ ln1b,
                         const float* __restrict__ ln2w,
                         const float* __restrict__ ln2b,
                         float* __restrict__ out,
                         float* sm, int blk)
{
    float* xs  = sm + XS_OFF;
    float* hs  = sm + HS_OFF;
    float* w1s = sm + W1_OFF;
    float* w2s = sm + W2_OFF;
    const uint32_t xsu = smem_u32(xs);
    const uint32_t w1u = smem_u32(w1s);
    const uint32_t w2u = smem_u32(w2s);

    const int tid = threadIdx.x, lane = tid & 31, wp = tid >> 5;
    const int g = lane >> 2, t = lane & 3;
    const int b = blk >> 7, row = blk & 127;

    // ---- acquire: wait for the 8 source windows ----
    if (tid == 0) {
        volatile int* f = &g_flags[b * 8 + (row >> 4)];
        while (*f < 8) __nanosleep(64);
        __threadfence();
    }
    __syncthreads();

    const int fr0 = (wp >> 2) * 16;
    const int px0 = (wp & 3) * 32;
    const int pxm0 = (wp & 3) * 32;
    const int c0w = (wp >> 2) * 128;

    // ---- group 1: W1(0) + xs (raw fp32, async) ----
    for (int j = 0; j < 8; j++) {
        int id = tid + j * 256;
        int f = id >> 6, seg = id & 63;
        CP16(w1u + (uint32_t)(f * 260 + seg * 4) * 4u, W1 + (size_t)f * CC + seg * 4);
    }
    {
        const float* xab = g_xa + (size_t)b * CC * HW + (size_t)row * WWD;
#pragma unroll 4
        for (int j = 0; j < 32; j++) {
            int id = tid + j * 256;
            int c = id >> 5, s = id & 31;
            CP16(xsu + (uint32_t)(c * 132 + s * 4) * 4u, xab + (size_t)c * HW + s * 4);
        }
    }
    CP_COMMIT();
    for (int j = 0; j < 8; j++) {
        int id = tid + j * 256;
        int c = id >> 3, seg = id & 7;
        CP16(w2u + (uint32_t)(c * 36 + seg * 4) * 4u, W2 + (size_t)c * FF + seg * 4);
    }
    CP_COMMIT();

    float yacc[2][16][4];
#pragma unroll
    for (int mf = 0; mf < 2; mf++)
#pragma unroll
        for (int nf = 0; nf < 16; nf++)
#pragma unroll
            for (int r = 0; r < 4; r++) yacc[mf][nf][r] = 0.f;

    const float* wr0 = w1s + (fr0 + g) * 260;
    const float* wr1 = wr0 + 8 * 260;
    const float* xb0 = xs + t * 132 + px0 + g;

    float d1[4][4];
#pragma unroll
    for (int nf = 0; nf < 4; nf++)
#pragma unroll
        for (int r = 0; r < 4; r++) d1[nf][r] = 0.f;

    CP_WAIT1();
    __syncthreads();
#pragma unroll 8
    for (int ks = 0; ks < 32; ks++) {
        int k = ks * 8;
        float a0 = wr0[k + t], a1 = wr1[k + t];
        float a2 = wr0[k + t + 4], a3 = wr1[k + t + 4];
        const float* xk = xb0 + k * 132;
#pragma unroll
        for (int nf = 0; nf < 4; nf++)
            mma_tf32(d1[nf], a0, a1, a2, a3, xk[nf * 8], xk[4 * 132 + nf * 8]);
    }
    __syncthreads();
    {
        const float* src = W1 + (size_t)32 * CC;
        for (int j = 0; j < 8; j++) {
            int id = tid + j * 256;
            int f = id >> 6, seg = id & 63;
            CP16(w1u + (uint32_t)(f * 260 + seg * 4) * 4u, src + (size_t)f * CC + seg * 4);
        }
        CP_COMMIT();
    }

    for (int ft = 0; ft < 32; ft++) {
        const int ftb = ft * 32;

        {
            float b1a = __ldg(&b1[ftb + fr0 + g]);
            float b1b = __ldg(&b1[ftb + fr0 + g + 8]);
#pragma unroll
            for (int nf = 0; nf < 4; nf++) {
                int px = px0 + nf * 8 + 2 * t;
                float2 v01 = make_float2(gelu_exact(d1[nf][0] + b1a),
                                         gelu_exact(d1[nf][1] + b1a));
                float2 v23 = make_float2(gelu_exact(d1[nf][2] + b1b),
                                         gelu_exact(d1[nf][3] + b1b));
                *(float2*)&hs[(fr0 + g) * 132 + px] = v01;
                *(float2*)&hs[(fr0 + g + 8) * 132 + px] = v23;
            }
        }
        CP_WAIT0();
        __syncthreads();

        float d1n[4][4];
#pragma unroll
        for (int nf = 0; nf < 4; nf++)
#pragma unroll
            for (int r = 0; r < 4; r++) d1n[nf][r] = 0.f;

        const bool more = (ft < 31);
#pragma unroll
        for (int ks2 = 0; ks2 < 4; ks2++) {
            const int k2 = ks2 * 8;
            float am[2][4];
#pragma unroll
            for (int mf = 0; mf < 2; mf++) {
                const float* hb = hs + (k2 + t) * 132 + pxm0 + 16 * mf + g;
                am[mf][0] = hb[0];
                am[mf][1] = hb[8];
                am[mf][2] = hb[4 * 132];
                am[mf][3] = hb[4 * 132 + 8];
            }
#pragma unroll
            for (int jj = 0; jj < 8; jj++) {
                if (more) {
                    int k = (ks2 * 8 + jj) * 8;
                    float a0 = wr0[k + t], a1 = wr1[k + t];
                    float a2 = wr0[k + t + 4], a3 = wr1[k + t + 4];
                    const float* xk = xb0 + k * 132;
#pragma unroll
                    for (int nf = 0; nf < 4; nf++)
                        mma_tf32(d1n[nf], a0, a1, a2, a3, xk[nf * 8], xk[4 * 132 + nf * 8]);
                }
#pragma unroll
                for (int u = 0; u < 2; u++) {
                    int nf = jj * 2 + u;
                    const float* wb = w2s + (c0w + nf * 8 + g) * 36 + k2 + t;
                    float b0 = wb[0], b1v = wb[4];
                    mma_tf32(yacc[0][nf], am[0][0], am[0][1], am[0][2], am[0][3], b0, b1v);
                    mma_tf32(yacc[1][nf], am[1][0], am[1][1], am[1][2], am[1][3], b0, b1v);
                }
            }
        }
        __syncthreads();

        if (ft < 31) {
            const float* src2 = W2 + (size_t)(ftb + 32);
            for (int j = 0; j < 8; j++) {
                int id = tid + j * 256;
                int c = id >> 3, seg = id & 7;
                CP16(w2u + (uint32_t)(c * 36 + seg * 4) * 4u, src2 + (size_t)c * FF + seg * 4);
            }
            if (ft < 30) {
                const float* src1 = W1 + (size_t)(ftb + 64) * CC;
                for (int j = 0; j < 8; j++) {
                    int id = tid + j * 256;
                    int f = id >> 6, seg = id & 63;
                    CP16(w1u + (uint32_t)(f * 260 + seg * 4) * 4u, src1 + (size_t)f * CC + seg * 4);
                }
            }
            CP_COMMIT();
        }

#pragma unroll
        for (int nf = 0; nf < 4; nf++)
#pragma unroll
            for (int r = 0; r < 4; r++) d1[nf][r] = d1n[nf][r];
    }
    __syncthreads();

    float* ys = sm;
#pragma unroll
    for (int nf = 0; nf < 16; nf++) {
        int c = c0w + nf * 8 + 2 * t;
        float b2a = __ldg(&b2[c]);
        float b2b = __ldg(&b2[c + 1]);
#pragma unroll
        for (int mf = 0; mf < 2; mf++) {
            int pxr = pxm0 + 16 * mf + g;
            *(float2*)&ys[pxr * 260 + c] =
                make_float2(yacc[mf][nf][0] + b2a, yacc[mf][nf][1] + b2b);
            *(float2*)&ys[(pxr + 8) * 260 + c] =
                make_float2(yacc[mf][nf][2] + b2a, yacc[mf][nf][3] + b2b);
        }
    }
    __syncthreads();

    int px = tid >> 1, hf = tid & 1;
    float* yrow = ys + px * 260 + hf * 128;
    float* red = hs;

    float s1 = 0.f, s2 = 0.f;
#pragma unroll 8
    for (int i = 0; i < 128; i += 4) {
        float4 v = *(float4*)&yrow[i];
        s1 += v.x + v.y + v.z + v.w;
        s2 += v.x * v.x + v.y * v.y + v.z * v.z + v.w * v.w;
    }
    red[tid] = s1; red[512 + tid] = s2;
    __syncthreads();
    float mu = (red[px * 2] + red[px * 2 + 1]) * (1.f / 256.f);
    float va = (red[512 + px * 2] + red[512 + px * 2 + 1]) * (1.f / 256.f);
    float rstd = rsqrtf(va - mu * mu + 1e-5f);

    const float* xsrc = g_xa + ((size_t)(b * CC) + hf * 128) * HW + (size_t)row * WWD + px;
    float t1 = 0.f, t2 = 0.f;
    for (int i = 0; i < 128; i++) {
        int c = hf * 128 + i;
        float x2v = xsrc[(size_t)i * HW] + (yrow[i] - mu) * rstd * ln1w[c] + ln1b[c];
        yrow[i] = x2v;
        t1 += x2v; t2 += x2v * x2v;
    }
    __syncthreads();
    red[tid] = t1; red[512 + tid] = t2;
    __syncthreads();
    float mu2 = (red[px * 2] + red[px * 2 + 1]) * (1.f / 256.f);
    float va2 = (red[512 + px * 2] + red[512 + px * 2 + 1]) * (1.f / 256.f);
    float rstd2 = rsqrtf(va2 - mu2 * mu2 + 1e-5f);

    float* op = out + ((size_t)(b * CC) + hf * 128) * HW + (size_t)row * WWD + px;
    for (int i = 0; i < 128; i++) {
        int c = hf * 128 + i;
        float v = yrow[i];
        op[(size_t)i * HW] = v + (v - mu2) * rstd2 * ln2w[c] + ln2b[c];
    }
}

// ------------------------------------------------------------------
__global__ void __launch_bounds__(256) fused_kernel(const float* __restrict__ x,
                                                    const float* __restrict__ Wq,
                                                    const float* __restrict__ Wk,
                                                    const float* __restrict__ Wv,
                                                    const float* __restrict__ gamma,
                                                    const float* __restrict__ W1,
                                                    const float* __restrict__ b1,
                                                    const float* __restrict__ W2,
                                                    const float* __restrict__ b2,
                                                    const float* __restrict__ ln1w,
                                                    const float* __restrict__ ln1b,
                                                    const float* __restrict__ ln2w,
                                                    const float* __restrict__ ln2b,
                                                    float* __restrict__ out)
{
    extern __shared__ __align__(16) char smraw[];
    if (blockIdx.x < NWIN) {
        attn_body(nullptr, x, Wq, Wk, Wv, gamma, smraw, blockIdx.x);
    } else {
        ffn_body(W1, b1, W2, b2, ln1w, ln1b, ln2w, ln2b, out,
                 (float*)smraw, blockIdx.x - NWIN);
    }
}

// ------------------------------------------------------------------
extern "C" void kernel_launch(void* const* d_in, const int* in_sizes, int n_in,
                              void* d_out, int out_size)
{
    const float* x    = (const float*)d_in[0];
    const float* Wq   = (const float*)d_in[1];
    const float* Wk   = (const float*)d_in[2];
    const float* Wv   = (const float*)d_in[3];
    const float* gam  = (const float*)d_in[4];
    const float* W1   = (const float*)d_in[5];
    const float* b1   = (const float*)d_in[6];
    const float* W2   = (const float*)d_in[7];
    const float* b2   = (const float*)d_in[8];
    const float* ln1w = (const float*)d_in[9];
    const float* ln1b = (const float*)d_in[10];
    const float* ln2w = (const float*)d_in[11];
    const float* ln2b = (const float*)d_in[12];
    float* out = (float*)d_out;

    cudaFuncSetAttribute(fused_kernel, cudaFuncAttributeMaxDynamicSharedMemorySize, FUSED_SMEM);

    reset_flags_kernel<<<1, 64>>>();
    fused_kernel<<<NWIN + BQ * HH, 256, FUSED_SMEM>>>(x, Wq, Wk, Wv, gam,
                                                      W1, b1, W2, b2,
                                                      ln1w, ln1b, ln2w, ln2b, out);
}